// round 12
// baseline (speedup 1.0000x reference)
#include <cuda_runtime.h>
#include <cuda_fp16.h>
#include <cstdint>

#define N_NODES 500000
#define N_EDGES 2000000
#define C       32
#define NGRAPH  1024
#define HIDDEN  1024
#define LAYERS  8

#define SCAN_BLK 256
#define ITEMS    8
#define CHUNK    (SCAN_BLK * ITEMS)                       // 2048
#define NBLK     ((N_NODES + CHUNK - 1) / CHUNK)          // 245

// ---------------- device scratch (static; zero-initialized at load) ----------
__device__ __half d_xh  [2][(size_t)N_NODES * C];         // fp16 feature ping/pong
__device__ int    d_cnt [2][N_NODES];                     // degrees (self-cleaned by scanC)
__device__ int    d_cur [2][N_NODES];                     // scatter cursors
__device__ int    d_csr [2][N_EDGES];
__device__ int4   d_meta[N_NODES];                        // {b0, d0, b1, d1}
__device__ int    d_bsum[2][NBLK];
__device__ float  d_gsum[NGRAPH * C];                     // self-cleaned by k_mlp
__device__ float  d_gcnt[NGRAPH];

// ---------------- degree histogram (d_cnt zeroed by previous scanC) -----------
__global__ void k_hist(const int* __restrict__ src, const int* __restrict__ dst, int E)
{
    int e = blockIdx.x * blockDim.x + threadIdx.x;
    if (e >= E) return;
    atomicAdd(&d_cnt[0][__ldg(dst + e)], 1);
    atomicAdd(&d_cnt[1][__ldg(src + e)], 1);
}

// ---------------- scan phase A: per-block sums --------------------------------
__global__ void k_scanA()
{
    int y = blockIdx.y;
    int base = blockIdx.x * CHUNK + threadIdx.x * ITEMS;
    int s = 0;
    #pragma unroll
    for (int j = 0; j < ITEMS; j++) {
        int i = base + j;
        if (i < N_NODES) s += d_cnt[y][i];
    }
    #pragma unroll
    for (int o = 16; o > 0; o >>= 1) s += __shfl_down_sync(0xffffffffu, s, o);
    __shared__ int sh[8];
    if ((threadIdx.x & 31) == 0) sh[threadIdx.x >> 5] = s;
    __syncthreads();
    if (threadIdx.x == 0) {
        int t = 0;
        #pragma unroll
        for (int w = 0; w < 8; w++) t += sh[w];
        d_bsum[y][blockIdx.x] = t;
    }
}

// ---------------- scan phase B: exclusive scan of block sums ------------------
__global__ void k_scanB()
{
    int y = blockIdx.y;
    int tid = threadIdx.x;
    int lane = tid & 31, warp = tid >> 5;
    int val = (tid < NBLK) ? d_bsum[y][tid] : 0;
    int incl = val;
    #pragma unroll
    for (int o = 1; o < 32; o <<= 1) {
        int t = __shfl_up_sync(0xffffffffu, incl, o);
        if (lane >= o) incl += t;
    }
    __shared__ int shw[8];
    if (lane == 31) shw[warp] = incl;
    __syncthreads();
    if (warp == 0 && lane < 8) {
        int b = shw[lane], ib = b;
        #pragma unroll
        for (int o = 1; o < 8; o <<= 1) {
            int t = __shfl_up_sync(0xffu, ib, o);
            if (lane >= o) ib += t;
        }
        shw[lane] = ib - b;
    }
    __syncthreads();
    if (tid < NBLK) d_bsum[y][tid] = shw[warp] + incl - val;
}

// ---------------- scan phase C: meta/cursors; re-zero counters ----------------
__global__ void k_scanC()
{
    int y = blockIdx.y;
    int lane = threadIdx.x & 31, warp = threadIdx.x >> 5;
    int base = blockIdx.x * CHUNK + threadIdx.x * ITEMS;

    int v[ITEMS]; int tsum = 0;
    #pragma unroll
    for (int j = 0; j < ITEMS; j++) {
        int i = base + j;
        v[j] = (i < N_NODES) ? d_cnt[y][i] : 0;
        tsum += v[j];
    }
    int incl = tsum;
    #pragma unroll
    for (int o = 1; o < 32; o <<= 1) {
        int t = __shfl_up_sync(0xffffffffu, incl, o);
        if (lane >= o) incl += t;
    }
    __shared__ int shw[8];
    if (lane == 31) shw[warp] = incl;
    __syncthreads();
    if (warp == 0 && lane < 8) {
        int b = shw[lane], ib = b;
        #pragma unroll
        for (int o = 1; o < 8; o <<= 1) {
            int t = __shfl_up_sync(0xffu, ib, o);
            if (lane >= o) ib += t;
        }
        shw[lane] = ib - b;
    }
    __syncthreads();
    int run = d_bsum[y][blockIdx.x] + shw[warp] + (incl - tsum);
    #pragma unroll
    for (int j = 0; j < ITEMS; j++) {
        int i = base + j;
        if (i < N_NODES) {
            int* mp = (int*)&d_meta[i];
            mp[y * 2 + 0] = run;          // base
            mp[y * 2 + 1] = v[j];         // degree
            d_cur[y][i]   = run;
            d_cnt[y][i]   = 0;            // self-clean for next call
            run += v[j];
        }
    }
}

// ---------------- fused CSR fill + feature init --------------------------------
__global__ void k_scatter_init(const int* __restrict__ src, const int* __restrict__ dst,
                               const int* __restrict__ nodes, const float* __restrict__ emb,
                               int E, int n)
{
    int idx = blockIdx.x * blockDim.x + threadIdx.x;
    if (idx < n * C) {
        int node = idx >> 5;
        int c    = idx & 31;
        int t    = __ldg(nodes + node);
        d_xh[0][idx] = __float2half_rn(__ldg(emb + t * C + c));
    }
    if (idx < E) {
        int s = __ldg(src + idx);
        int t = __ldg(dst + idx);
        int p = atomicAdd(&d_cur[0][t], 1);  d_csr[0][p] = s;
        int q = atomicAdd(&d_cur[1][s], 1);  d_csr[1][q] = t;
    }
}

// ---------------- mma.m16n8k16 helper -------------------------------------------
__device__ __forceinline__ void mma_16816(float* d,
                                          uint32_t a0, uint32_t a1, uint32_t a2, uint32_t a3,
                                          uint32_t b0, uint32_t b1)
{
    asm volatile(
        "mma.sync.aligned.m16n8k16.row.col.f32.f16.f16.f32 "
        "{%0,%1,%2,%3}, {%4,%5,%6,%7}, {%8,%9}, {%0,%1,%2,%3};"
        : "+f"(d[0]), "+f"(d[1]), "+f"(d[2]), "+f"(d[3])
        : "r"(a0), "r"(a1), "r"(a2), "r"(a3), "r"(b0), "r"(b1));
}

#define CAPI 512

// ---- gather pipeline stages (inlined; all args by value / reference-to-reg) ----
__device__ __forceinline__ void gather_issue(
    int nl, int lastLocal, int blockBase,
    const __half* __restrict__ xin,
    const int4* s_meta, int beg0, int beg1, const int (*s_idx)[CAPI],
    int cq, int rs,
    int4& m, uint2& xr, uint2& l0, uint2& l1, uint2& l2, uint2& l3)
{
    bool valid = nl < lastLocal;
    m = valid ? s_meta[nl] : make_int4(beg0, 0, beg1, 0);
    uint2 z = make_uint2(0u, 0u);
    xr = valid ? __ldg((const uint2*)(xin + (size_t)(blockBase + nl) * C) + cq) : z;
    int o0 = m.x - beg0, o1 = m.z - beg1;
    l0 = z; l1 = z; l2 = z; l3 = z;
    if (rs < m.y) {
        int p = o0 + rs;
        int s = (p < CAPI) ? s_idx[0][p] : __ldg(&d_csr[0][beg0 + p]);
        l0 = __ldg((const uint2*)(xin + (size_t)s * C) + cq);
    }
    if (rs + 4 < m.y) {
        int p = o0 + rs + 4;
        int s = (p < CAPI) ? s_idx[0][p] : __ldg(&d_csr[0][beg0 + p]);
        l1 = __ldg((const uint2*)(xin + (size_t)s * C) + cq);
    }
    if (rs < m.w) {
        int p = o1 + rs;
        int s = (p < CAPI) ? s_idx[1][p] : __ldg(&d_csr[1][beg1 + p]);
        l2 = __ldg((const uint2*)(xin + (size_t)s * C) + cq);
    }
    if (rs + 4 < m.w) {
        int p = o1 + rs + 4;
        int s = (p < CAPI) ? s_idx[1][p] : __ldg(&d_csr[1][beg1 + p]);
        l3 = __ldg((const uint2*)(xin + (size_t)s * C) + cq);
    }
}

__device__ __forceinline__ void gather_finish(
    int nl, const __half* __restrict__ xin,
    int beg0, int beg1, const int (*s_idx)[CAPI],
    int cq, int rs,
    int4 m, uint2 xr, uint2 l0, uint2 l1, uint2 l2, uint2 l3,
    __half (*s_h0)[32], __half (*s_h1)[32], __half (*s_x)[32])
{
    const unsigned FULL = 0xffffffffu;
    float2 xa = __half22float2(*(__half2*)&xr.x);
    float2 xb = __half22float2(*(__half2*)&xr.y);
    float f0, f1, f2, f3;
    if (rs == 0) { f0 = xa.x; f1 = xa.y; f2 = xb.x; f3 = xb.y; }
    else         { f0 = 0.f;  f1 = 0.f;  f2 = 0.f;  f3 = 0.f; }
    float g0 = f0, g1 = f1, g2 = f2, g3 = f3;

    float2 t0, t1;
    t0 = __half22float2(*(__half2*)&l0.x); t1 = __half22float2(*(__half2*)&l0.y);
    f0 += t0.x; f1 += t0.y; f2 += t1.x; f3 += t1.y;
    t0 = __half22float2(*(__half2*)&l1.x); t1 = __half22float2(*(__half2*)&l1.y);
    f0 += t0.x; f1 += t0.y; f2 += t1.x; f3 += t1.y;
    t0 = __half22float2(*(__half2*)&l2.x); t1 = __half22float2(*(__half2*)&l2.y);
    g0 += t0.x; g1 += t0.y; g2 += t1.x; g3 += t1.y;
    t0 = __half22float2(*(__half2*)&l3.x); t1 = __half22float2(*(__half2*)&l3.y);
    g0 += t0.x; g1 += t0.y; g2 += t1.x; g3 += t1.y;

    // rare tail (deg > 8)
    int p0 = m.y < 8 ? m.y : 8;
    int p1 = m.w < 8 ? m.w : 8;
    if (p0 < m.y || p1 < m.w) {
        int o0 = m.x - beg0, o1 = m.z - beg1;
        while (p0 < m.y || p1 < m.w) {
            int n0 = m.y - p0; if (n0 < 0) n0 = 0; if (n0 > 4) n0 = 4;
            int n1 = m.w - p1; if (n1 < 0) n1 = 0; if (n1 > 4) n1 = 4;
            uint2 v0 = make_uint2(0u, 0u), v1 = make_uint2(0u, 0u);
            if (rs < n0) {
                int p = o0 + p0 + rs;
                int s = (p < CAPI) ? s_idx[0][p] : __ldg(&d_csr[0][beg0 + p]);
                v0 = __ldg((const uint2*)(xin + (size_t)s * C) + cq);
            }
            if (rs < n1) {
                int p = o1 + p1 + rs;
                int s = (p < CAPI) ? s_idx[1][p] : __ldg(&d_csr[1][beg1 + p]);
                v1 = __ldg((const uint2*)(xin + (size_t)s * C) + cq);
            }
            t0 = __half22float2(*(__half2*)&v0.x); t1 = __half22float2(*(__half2*)&v0.y);
            f0 += t0.x; f1 += t0.y; f2 += t1.x; f3 += t1.y;
            t0 = __half22float2(*(__half2*)&v1.x); t1 = __half22float2(*(__half2*)&v1.y);
            g0 += t0.x; g1 += t0.y; g2 += t1.x; g3 += t1.y;
            p0 += n0; p1 += n1;
        }
    }

    f0 += __shfl_xor_sync(FULL, f0, 8);  f0 += __shfl_xor_sync(FULL, f0, 16);
    f1 += __shfl_xor_sync(FULL, f1, 8);  f1 += __shfl_xor_sync(FULL, f1, 16);
    f2 += __shfl_xor_sync(FULL, f2, 8);  f2 += __shfl_xor_sync(FULL, f2, 16);
    f3 += __shfl_xor_sync(FULL, f3, 8);  f3 += __shfl_xor_sync(FULL, f3, 16);
    g0 += __shfl_xor_sync(FULL, g0, 8);  g0 += __shfl_xor_sync(FULL, g0, 16);
    g1 += __shfl_xor_sync(FULL, g1, 8);  g1 += __shfl_xor_sync(FULL, g1, 16);
    g2 += __shfl_xor_sync(FULL, g2, 8);  g2 += __shfl_xor_sync(FULL, g2, 16);
    g3 += __shfl_xor_sync(FULL, g3, 8);  g3 += __shfl_xor_sync(FULL, g3, 16);

    float nf = __fdividef(1.f, 1.f + (float)m.y);
    float nb = __fdividef(1.f, 1.f + (float)m.w);

    if (rs == 0) {
        __half2 hf0 = __floats2half2_rn(f0 * nf, f1 * nf);
        __half2 hf1 = __floats2half2_rn(f2 * nf, f3 * nf);
        __half2 hb0 = __floats2half2_rn(g0 * nb, g1 * nb);
        __half2 hb1 = __floats2half2_rn(g2 * nb, g3 * nb);
        uint2 pf; pf.x = *(uint32_t*)&hf0; pf.y = *(uint32_t*)&hf1;
        uint2 pb; pb.x = *(uint32_t*)&hb0; pb.y = *(uint32_t*)&hb1;
        *(uint2*)&s_h0[nl][cq * 4] = pf;
        *(uint2*)&s_h1[nl][cq * 4] = pb;
        *(uint2*)&s_x [nl][cq * 4] = xr;
    }
}

// ---------------- fused layer: depth-3 pipelined gather -> split-warp mma ------
// 256 threads = 8 warps; 64 nodes/block. Gather: rotating 3-node pipeline.
// GEMM: warps 0..7 = (dir, m-tile); dir-1 hands fp32 results via reused smem.
__global__ void __launch_bounds__(256, 3) k_layer(const __half* __restrict__ xin,
                                                  __half* __restrict__ xout,
                                                  const float* __restrict__ w, int n)
{
    __shared__ __half s_wt[2][32][32];   // 4 KB transposed weights
    __shared__ __half s_h [2][64][32];   // 8 KB aggregated features (later: fp32 handoff)
    __shared__ __half s_x [64][32];      // 4 KB residual
    __shared__ int4   s_meta[64];        // 1 KB node meta
    __shared__ int    s_idx[2][CAPI];    // 4 KB CSR slices

    const int tid  = threadIdx.x;
    const int lane = tid & 31;
    const int warp = tid >> 5;
    const int cq   = lane & 7;
    const int rs   = lane >> 3;
    const int blockBase = blockIdx.x * 64;
    const int lastLocal = min(64, n - blockBase);

    for (int i = tid; i < 2 * 32 * 32; i += 256) {
        int d = i >> 10, rem = i & 1023, k = rem >> 5, j = rem & 31;
        s_wt[d][j][k] = __float2half_rn(__ldg(w + d * 1024 + k * 32 + j));
    }
    if (tid < 64) {
        s_meta[tid] = (tid < lastLocal) ? __ldg(&d_meta[blockBase + tid])
                                        : make_int4(0, 0, 0, 0);
    }
    __syncthreads();

    const int4 mF = s_meta[0];
    const int4 mL = s_meta[lastLocal - 1];
    const int beg0 = mF.x, len0 = mL.x + mL.y - mF.x;
    const int beg1 = mF.z, len1 = mL.z + mL.w - mF.z;
    for (int i = tid; i < min(len0, CAPI); i += 256) s_idx[0][i] = __ldg(&d_csr[0][beg0 + i]);
    for (int i = tid; i < min(len1, CAPI); i += 256) s_idx[1][i] = __ldg(&d_csr[1][beg1 + i]);
    __syncthreads();

    // ---- gather: rotating depth-3 pipeline over this warp's 8 nodes ----
    {
        const int nbase = warp * 8;
        int4  M[3]; uint2 XR[3], A[3], B[3], Cc[3], D[3];
        #pragma unroll
        for (int i = 0; i < 3; i++)
            gather_issue(nbase + i, lastLocal, blockBase, xin, s_meta, beg0, beg1,
                         s_idx, cq, rs, M[i], XR[i], A[i], B[i], Cc[i], D[i]);
        #pragma unroll
        for (int i = 0; i < 8; i++) {
            const int b = i % 3;
            gather_finish(nbase + i, xin, beg0, beg1, s_idx, cq, rs,
                          M[b], XR[b], A[b], B[b], Cc[b], D[b],
                          s_h[0], s_h[1], s_x);
            if (i + 3 < 8)
                gather_issue(nbase + i + 3, lastLocal, blockBase, xin, s_meta, beg0, beg1,
                             s_idx, cq, rs, M[b], XR[b], A[b], B[b], Cc[b], D[b]);
        }
    }
    __syncthreads();

    // ---- GEMM: warp = (dir, m-tile); 16 fp32 accumulators per warp ----
    const int dir  = warp >> 2;          // 0..1
    const int wm   = warp & 3;           // m-tile 0..3
    const int g    = lane >> 2;
    const int t    = lane & 3;
    const int m0   = wm * 16;

    float acc[4][4];
    #pragma unroll
    for (int nt = 0; nt < 4; nt++)
        #pragma unroll
        for (int i = 0; i < 4; i++) acc[nt][i] = 0.f;

    #pragma unroll
    for (int kt = 0; kt < 32; kt += 16) {
        uint32_t a0 = *(const uint32_t*)&s_h[dir][m0 + g    ][kt + t * 2];
        uint32_t a1 = *(const uint32_t*)&s_h[dir][m0 + g + 8][kt + t * 2];
        uint32_t a2 = *(const uint32_t*)&s_h[dir][m0 + g    ][kt + t * 2 + 8];
        uint32_t a3 = *(const uint32_t*)&s_h[dir][m0 + g + 8][kt + t * 2 + 8];
        #pragma unroll
        for (int nt = 0; nt < 4; nt++) {
            uint32_t b0 = *(const uint32_t*)&s_wt[dir][nt * 8 + g][kt + t * 2];
            uint32_t b1 = *(const uint32_t*)&s_wt[dir][nt * 8 + g][kt + t * 2 + 8];
            mma_16816(acc[nt], a0, a1, a2, a3, b0, b1);
        }
    }
    __syncthreads();   // all s_h reads done -> safe to overwrite as fp32 buffer

    float (*s_f)[32] = (float(*)[32])s_h;   // 8 KB fp32 handoff [64][32]
    if (dir == 1) {
        #pragma unroll
        for (int nt = 0; nt < 4; nt++) {
            int col = nt * 8 + t * 2;
            *(float2*)&s_f[m0 + g    ][col] =
                make_float2(fmaxf(acc[nt][0], 0.f), fmaxf(acc[nt][1], 0.f));
            *(float2*)&s_f[m0 + g + 8][col] =
                make_float2(fmaxf(acc[nt][2], 0.f), fmaxf(acc[nt][3], 0.f));
        }
    }
    __syncthreads();

    if (dir == 0) {
        int node0 = blockBase + m0 + g;
        int node1 = node0 + 8;
        #pragma unroll
        for (int nt = 0; nt < 4; nt++) {
            int col = nt * 8 + t * 2;
            float2 xv0 = __half22float2(*(__half2*)&s_x[m0 + g    ][col]);
            float2 xv1 = __half22float2(*(__half2*)&s_x[m0 + g + 8][col]);
            float2 b0  = *(float2*)&s_f[m0 + g    ][col];
            float2 b1  = *(float2*)&s_f[m0 + g + 8][col];
            float o00 = xv0.x + fmaxf(acc[nt][0], 0.f) + b0.x;
            float o01 = xv0.y + fmaxf(acc[nt][1], 0.f) + b0.y;
            float o10 = xv1.x + fmaxf(acc[nt][2], 0.f) + b1.x;
            float o11 = xv1.y + fmaxf(acc[nt][3], 0.f) + b1.y;
            if (node0 < n)
                *(__half2*)&xout[(size_t)node0 * C + col] = __floats2half2_rn(o00, o01);
            if (node1 < n)
                *(__half2*)&xout[(size_t)node1 * C + col] = __floats2half2_rn(o10, o11);
        }
    }
}

// ---------------- pooling: per-graph sum + count (batch sorted) ----------------
__global__ void k_pool(const int* __restrict__ batch, const __half* __restrict__ x, int n)
{
    int lane = threadIdx.x & 31;
    int warp = threadIdx.x >> 5;
    int base = blockIdx.x * 256 + warp * 32;

    float acc = 0.f;
    int cur = -1, run = 0;
    for (int j = 0; j < 32; j++) {
        int node = base + j;
        if (node >= n) break;
        int b = __ldg(batch + node);
        float v = __half2float(__ldg(x + (size_t)node * C + lane));
        if (b != cur) {
            if (cur >= 0) {
                atomicAdd(&d_gsum[cur * C + lane], acc);
                if (lane == 0) atomicAdd(&d_gcnt[cur], (float)run);
            }
            cur = b; acc = 0.f; run = 0;
        }
        acc += v; run++;
    }
    if (cur >= 0) {
        atomicAdd(&d_gsum[cur * C + lane], acc);
        if (lane == 0) atomicAdd(&d_gcnt[cur], (float)run);
    }
}

// ---------------- MLP head: 8 graphs per block; self-cleans pool buffers -------
#define GPB 8
__global__ void k_mlp(const float* __restrict__ hw, const float* __restrict__ hb,
                      const float* __restrict__ ow, float* __restrict__ out)
{
    __shared__ float gs[GPB][C];
    __shared__ float sout[GPB];
    int tid = threadIdx.x;
    if (tid < GPB * C) {
        int g = tid >> 5, c = tid & 31;
        int gb = blockIdx.x * GPB + g;
        gs[g][c] = d_gsum[gb * C + c] / d_gcnt[gb];
    }
    if (tid < GPB) sout[tid] = 0.f;
    __syncthreads();
    if (tid < GPB * C) {
        int g = tid >> 5, c = tid & 31;
        d_gsum[(blockIdx.x * GPB + g) * C + c] = 0.f;
    }
    if (tid < GPB) d_gcnt[blockIdx.x * GPB + tid] = 0.f;

    float part[GPB];
    #pragma unroll
    for (int g = 0; g < GPB; g++) part[g] = 0.f;

    for (int j = tid; j < HIDDEN; j += 256) {
        float h[GPB];
        float bj = __ldg(hb + j);
        #pragma unroll
        for (int g = 0; g < GPB; g++) h[g] = bj;
        #pragma unroll
        for (int k = 0; k < C; k++) {
            float wkj = __ldg(hw + k * HIDDEN + j);
            #pragma unroll
            for (int g = 0; g < GPB; g++)
                h[g] = fmaf(gs[g][k], wkj, h[g]);
        }
        float oj = __ldg(ow + j);
        #pragma unroll
        for (int g = 0; g < GPB; g++)
            part[g] += fmaxf(h[g], 0.f) * oj;
    }
    #pragma unroll
    for (int g = 0; g < GPB; g++) {
        float v = part[g];
        #pragma unroll
        for (int off = 16; off > 0; off >>= 1)
            v += __shfl_down_sync(0xffffffffu, v, off);
        if ((tid & 31) == 0) atomicAdd(&sout[g], v);
    }
    __syncthreads();
    if (tid < GPB) out[blockIdx.x * GPB + tid] = sout[tid];
}

// ---------------- launch ---------------------------------------------------------
extern "C" void kernel_launch(void* const* d_in, const int* in_sizes, int n_in,
                              void* d_out, int out_size)
{
    const int*   nodes    = (const int*)  d_in[0];
    const int*   sources  = (const int*)  d_in[1];
    const int*   targets  = (const int*)  d_in[2];
    const int*   batch    = (const int*)  d_in[3];
    const float* emb      = (const float*)d_in[4];
    const float* conv_w   = (const float*)d_in[5];
    const float* hidden_w = (const float*)d_in[6];
    const float* hidden_b = (const float*)d_in[7];
    const float* out_w    = (const float*)d_in[8];
    float*       out      = (float*)d_out;

    const int N = in_sizes[0];
    const int E = in_sizes[1];

    // CSR build
    k_hist        <<<(E + 255) / 256, 256>>>(sources, targets, E);
    k_scanA       <<<dim3(NBLK, 2), SCAN_BLK>>>();
    k_scanB       <<<dim3(1, 2),    SCAN_BLK>>>();
    k_scanC       <<<dim3(NBLK, 2), SCAN_BLK>>>();
    k_scatter_init<<<(N * C + 255) / 256, 256>>>(sources, targets, nodes, emb, E, N);

    // 8 fused layers, ping-pong (even count -> final in buffer 0)
    const int nb = (N + 63) / 64;
    __half* xh = nullptr;
    cudaGetSymbolAddress((void**)&xh, d_xh);
    __half* xa = xh;
    __half* xb = xh + (size_t)N_NODES * C;
    for (int l = 0; l < LAYERS; l++) {
        const float* wl = conv_w + (size_t)l * 2 * C * C;
        if ((l & 1) == 0) k_layer<<<nb, 256>>>(xa, xb, wl, N);
        else              k_layer<<<nb, 256>>>(xb, xa, wl, N);
    }
    k_pool<<<(N + 255) / 256, 256>>>(batch, xa, N);

    k_mlp<<<NGRAPH / GPB, 256>>>(hidden_w, hidden_b, out_w, out);
}

// round 13
// speedup vs baseline: 1.2976x; 1.2976x over previous
#include <cuda_runtime.h>
#include <cuda_fp16.h>
#include <cstdint>

#define N_NODES 500000
#define N_EDGES 2000000
#define C       32
#define NGRAPH  1024
#define HIDDEN  1024
#define LAYERS  8

#define SCAN_BLK 256
#define ITEMS    8
#define CHUNK    (SCAN_BLK * ITEMS)                       // 2048
#define NBLK     ((N_NODES + CHUNK - 1) / CHUNK)          // 245

// ---------------- device scratch (static; zero-initialized at load) ----------
__device__ __half d_xh  [2][(size_t)N_NODES * C];         // fp16 feature ping/pong
__device__ int    d_cnt [2][N_NODES];                     // degrees (self-cleaned by k_scan)
__device__ int    d_cur [2][N_NODES];                     // scatter cursors
__device__ int    d_csr [2][N_EDGES];
__device__ int4   d_meta[N_NODES];                        // {b0, d0, b1, d1}
__device__ int    d_agg [2][NBLK];                        // scan block aggregates
__device__ int    d_flag[2][NBLK];                        // publish flags (reset by k_hist)
__device__ float  d_gsum[NGRAPH * C];                     // self-cleaned by k_mlp
__device__ float  d_gcnt[NGRAPH];

// ---------------- degree histogram + scan-flag reset ---------------------------
__global__ void k_hist(const int* __restrict__ src, const int* __restrict__ dst, int E)
{
    int e = blockIdx.x * blockDim.x + threadIdx.x;
    if (e < 2 * NBLK) ((int*)d_flag)[e] = 0;    // reset flags for this call's k_scan
    if (e >= E) return;
    atomicAdd(&d_cnt[0][__ldg(dst + e)], 1);
    atomicAdd(&d_cnt[1][__ldg(src + e)], 1);
}

// ---------------- single-pass scan: publish aggregate, lookback, write meta ----
__global__ void k_scan()
{
    int y   = blockIdx.y;
    int bid = blockIdx.x;
    int tid = threadIdx.x;
    int lane = tid & 31, warp = tid >> 5;
    int base_i = bid * CHUNK + tid * ITEMS;

    int v[ITEMS]; int tsum = 0;
    #pragma unroll
    for (int j = 0; j < ITEMS; j++) {
        int i = base_i + j;
        v[j] = (i < N_NODES) ? d_cnt[y][i] : 0;
        tsum += v[j];
    }
    int incl = tsum;
    #pragma unroll
    for (int o = 1; o < 32; o <<= 1) {
        int t = __shfl_up_sync(0xffffffffu, incl, o);
        if (lane >= o) incl += t;
    }
    __shared__ int shw[8];
    __shared__ int s_tot;
    if (lane == 31) shw[warp] = incl;
    __syncthreads();
    if (warp == 0 && lane < 8) {
        int b = shw[lane], ib = b;
        #pragma unroll
        for (int o = 1; o < 8; o <<= 1) {
            int t = __shfl_up_sync(0xffu, ib, o);
            if (lane >= o) ib += t;
        }
        shw[lane] = ib - b;                     // exclusive warp base
        if (lane == 7) s_tot = ib;              // block total
    }
    __syncthreads();

    // publish this block's aggregate
    if (tid == 0) {
        d_agg[y][bid] = s_tot;
        __threadfence();
        d_flag[y][bid] = 1;
    }

    // lookback: sum all predecessors' aggregates (<=244; all blocks co-resident)
    __shared__ int s_red[SCAN_BLK];
    int a = 0;
    if (tid < bid) {
        volatile int* fl = &d_flag[y][0];
        while (fl[tid] == 0) { }
        __threadfence();
        a = *((volatile int*)&d_agg[y][tid]);
    }
    s_red[tid] = a;
    __syncthreads();
    #pragma unroll
    for (int o = SCAN_BLK / 2; o > 0; o >>= 1) {
        if (tid < o) s_red[tid] += s_red[tid + o];
        __syncthreads();
    }
    int run = s_red[0] + shw[warp] + (incl - tsum);

    #pragma unroll
    for (int j = 0; j < ITEMS; j++) {
        int i = base_i + j;
        if (i < N_NODES) {
            int* mp = (int*)&d_meta[i];
            mp[y * 2 + 0] = run;          // base
            mp[y * 2 + 1] = v[j];         // degree
            d_cur[y][i]   = run;
            d_cnt[y][i]   = 0;            // self-clean for next call
            run += v[j];
        }
    }
}

// ---------------- fused CSR fill + feature init --------------------------------
__global__ void k_scatter_init(const int* __restrict__ src, const int* __restrict__ dst,
                               const int* __restrict__ nodes, const float* __restrict__ emb,
                               int E, int n)
{
    int idx = blockIdx.x * blockDim.x + threadIdx.x;
    if (idx < n * C) {
        int node = idx >> 5;
        int c    = idx & 31;
        int t    = __ldg(nodes + node);
        d_xh[0][idx] = __float2half_rn(__ldg(emb + t * C + c));
    }
    if (idx < E) {
        int s = __ldg(src + idx);
        int t = __ldg(dst + idx);
        int p = atomicAdd(&d_cur[0][t], 1);  d_csr[0][p] = s;
        int q = atomicAdd(&d_cur[1][s], 1);  d_csr[1][q] = t;
    }
}

// ---------------- mma.m16n8k16 helper -------------------------------------------
__device__ __forceinline__ void mma_16816(float* d,
                                          uint32_t a0, uint32_t a1, uint32_t a2, uint32_t a3,
                                          uint32_t b0, uint32_t b1)
{
    asm volatile(
        "mma.sync.aligned.m16n8k16.row.col.f32.f16.f16.f32 "
        "{%0,%1,%2,%3}, {%4,%5,%6,%7}, {%8,%9}, {%0,%1,%2,%3};"
        : "+f"(d[0]), "+f"(d[1]), "+f"(d[2]), "+f"(d[3])
        : "r"(a0), "r"(a1), "r"(a2), "r"(a3), "r"(b0), "r"(b1));
}

// ---------------- fused layer: staged CSR -> pipelined 8-wide gather -> mma ----
// (exact R11 kernel — best known: pair-pipelined loads, deg<=8 fast path)
#define CAPI 512
__global__ void __launch_bounds__(256) k_layer(const __half* __restrict__ xin,
                                               __half* __restrict__ xout,
                                               const float* __restrict__ w, int n)
{
    __shared__ __half s_wt[2][32][32];   // 4 KB transposed weights
    __shared__ __half s_h [2][64][32];   // 8 KB aggregated features
    __shared__ __half s_x [64][32];      // 4 KB residual
    __shared__ int4   s_meta[64];        // 1 KB node meta
    __shared__ int    s_idx[2][CAPI];    // 4 KB CSR slices

    const int tid  = threadIdx.x;
    const int lane = tid & 31;
    const int warp = tid >> 5;
    const int cq   = lane & 7;            // channel quad (4 halves = 8 B)
    const int rs   = lane >> 3;           // row-in-batch 0..3
    const int blockBase = blockIdx.x * 64;
    const int lastLocal = min(64, n - blockBase);
    const unsigned FULL = 0xffffffffu;

    for (int i = tid; i < 2 * 32 * 32; i += 256) {
        int d = i >> 10, rem = i & 1023, k = rem >> 5, j = rem & 31;
        s_wt[d][j][k] = __float2half_rn(__ldg(w + d * 1024 + k * 32 + j));
    }
    if (tid < 64) {
        s_meta[tid] = (tid < lastLocal) ? __ldg(&d_meta[blockBase + tid])
                                        : make_int4(0, 0, 0, 0);
    }
    __syncthreads();

    const int4 mF = s_meta[0];
    const int4 mL = s_meta[lastLocal - 1];
    const int beg0 = mF.x, len0 = mL.x + mL.y - mF.x;
    const int beg1 = mF.z, len1 = mL.z + mL.w - mF.z;
    for (int i = tid; i < min(len0, CAPI); i += 256) s_idx[0][i] = __ldg(&d_csr[0][beg0 + i]);
    for (int i = tid; i < min(len1, CAPI); i += 256) s_idx[1][i] = __ldg(&d_csr[1][beg1 + i]);
    __syncthreads();

    // ---- gather: node pairs, stage-A loads then stage-B accumulate ----
    #pragma unroll
    for (int ni = 0; ni < 8; ni += 2) {
        int4  mA [2];
        uint2 xrA[2];
        uint2 w0a[2], w0b[2], w1a[2], w1b[2];

        // stage A: issue ALL loads for both nodes (independent)
        #pragma unroll
        for (int u = 0; u < 2; u++) {
            int nl = warp * 8 + ni + u;
            bool valid = nl < lastLocal;
            int4 m = valid ? s_meta[nl] : make_int4(beg0, 0, beg1, 0);
            mA[u] = m;
            uint2 z = make_uint2(0u, 0u);
            xrA[u] = valid ? __ldg((const uint2*)(xin + (size_t)(blockBase + nl) * C) + cq) : z;
            int o0 = m.x - beg0, o1 = m.z - beg1;
            w0a[u] = z; w0b[u] = z; w1a[u] = z; w1b[u] = z;
            if (rs < m.y) {
                int p = o0 + rs;
                int s = (p < CAPI) ? s_idx[0][p] : __ldg(&d_csr[0][beg0 + p]);
                w0a[u] = __ldg((const uint2*)(xin + (size_t)s * C) + cq);
            }
            if (rs + 4 < m.y) {
                int p = o0 + rs + 4;
                int s = (p < CAPI) ? s_idx[0][p] : __ldg(&d_csr[0][beg0 + p]);
                w0b[u] = __ldg((const uint2*)(xin + (size_t)s * C) + cq);
            }
            if (rs < m.w) {
                int p = o1 + rs;
                int s = (p < CAPI) ? s_idx[1][p] : __ldg(&d_csr[1][beg1 + p]);
                w1a[u] = __ldg((const uint2*)(xin + (size_t)s * C) + cq);
            }
            if (rs + 4 < m.w) {
                int p = o1 + rs + 4;
                int s = (p < CAPI) ? s_idx[1][p] : __ldg(&d_csr[1][beg1 + p]);
                w1b[u] = __ldg((const uint2*)(xin + (size_t)s * C) + cq);
            }
        }

        // stage B: accumulate, (rare) tail, reduce, store
        #pragma unroll
        for (int u = 0; u < 2; u++) {
            int nl = warp * 8 + ni + u;
            int4 m = mA[u];
            float2 xa = __half22float2(*(__half2*)&xrA[u].x);
            float2 xb = __half22float2(*(__half2*)&xrA[u].y);
            float f0, f1, f2, f3;
            if (rs == 0) { f0 = xa.x; f1 = xa.y; f2 = xb.x; f3 = xb.y; }
            else         { f0 = 0.f;  f1 = 0.f;  f2 = 0.f;  f3 = 0.f; }
            float g0 = f0, g1 = f1, g2 = f2, g3 = f3;

            float2 t0, t1;
            t0 = __half22float2(*(__half2*)&w0a[u].x);
            t1 = __half22float2(*(__half2*)&w0a[u].y);
            f0 += t0.x; f1 += t0.y; f2 += t1.x; f3 += t1.y;
            t0 = __half22float2(*(__half2*)&w0b[u].x);
            t1 = __half22float2(*(__half2*)&w0b[u].y);
            f0 += t0.x; f1 += t0.y; f2 += t1.x; f3 += t1.y;
            t0 = __half22float2(*(__half2*)&w1a[u].x);
            t1 = __half22float2(*(__half2*)&w1a[u].y);
            g0 += t0.x; g1 += t0.y; g2 += t1.x; g3 += t1.y;
            t0 = __half22float2(*(__half2*)&w1b[u].x);
            t1 = __half22float2(*(__half2*)&w1b[u].y);
            g0 += t0.x; g1 += t0.y; g2 += t1.x; g3 += t1.y;

            // rare tail (deg > 8)
            int p0 = m.y < 8 ? m.y : 8;
            int p1 = m.w < 8 ? m.w : 8;
            if (p0 < m.y || p1 < m.w) {
                int o0 = m.x - beg0, o1 = m.z - beg1;
                while (p0 < m.y || p1 < m.w) {
                    int n0 = m.y - p0; if (n0 < 0) n0 = 0; if (n0 > 4) n0 = 4;
                    int n1 = m.w - p1; if (n1 < 0) n1 = 0; if (n1 > 4) n1 = 4;
                    uint2 v0 = make_uint2(0u, 0u), v1 = make_uint2(0u, 0u);
                    if (rs < n0) {
                        int p = o0 + p0 + rs;
                        int s = (p < CAPI) ? s_idx[0][p] : __ldg(&d_csr[0][beg0 + p]);
                        v0 = __ldg((const uint2*)(xin + (size_t)s * C) + cq);
                    }
                    if (rs < n1) {
                        int p = o1 + p1 + rs;
                        int s = (p < CAPI) ? s_idx[1][p] : __ldg(&d_csr[1][beg1 + p]);
                        v1 = __ldg((const uint2*)(xin + (size_t)s * C) + cq);
                    }
                    t0 = __half22float2(*(__half2*)&v0.x);
                    t1 = __half22float2(*(__half2*)&v0.y);
                    f0 += t0.x; f1 += t0.y; f2 += t1.x; f3 += t1.y;
                    t0 = __half22float2(*(__half2*)&v1.x);
                    t1 = __half22float2(*(__half2*)&v1.y);
                    g0 += t0.x; g1 += t0.y; g2 += t1.x; g3 += t1.y;
                    p0 += n0; p1 += n1;
                }
            }

            // reduce over the 4 row-groups
            f0 += __shfl_xor_sync(FULL, f0, 8);  f0 += __shfl_xor_sync(FULL, f0, 16);
            f1 += __shfl_xor_sync(FULL, f1, 8);  f1 += __shfl_xor_sync(FULL, f1, 16);
            f2 += __shfl_xor_sync(FULL, f2, 8);  f2 += __shfl_xor_sync(FULL, f2, 16);
            f3 += __shfl_xor_sync(FULL, f3, 8);  f3 += __shfl_xor_sync(FULL, f3, 16);
            g0 += __shfl_xor_sync(FULL, g0, 8);  g0 += __shfl_xor_sync(FULL, g0, 16);
            g1 += __shfl_xor_sync(FULL, g1, 8);  g1 += __shfl_xor_sync(FULL, g1, 16);
            g2 += __shfl_xor_sync(FULL, g2, 8);  g2 += __shfl_xor_sync(FULL, g2, 16);
            g3 += __shfl_xor_sync(FULL, g3, 8);  g3 += __shfl_xor_sync(FULL, g3, 16);

            float nf = __fdividef(1.f, 1.f + (float)m.y);
            float nb = __fdividef(1.f, 1.f + (float)m.w);

            if (rs == 0) {
                __half2 hf0 = __floats2half2_rn(f0 * nf, f1 * nf);
                __half2 hf1 = __floats2half2_rn(f2 * nf, f3 * nf);
                __half2 hb0 = __floats2half2_rn(g0 * nb, g1 * nb);
                __half2 hb1 = __floats2half2_rn(g2 * nb, g3 * nb);
                uint2 pf; pf.x = *(uint32_t*)&hf0; pf.y = *(uint32_t*)&hf1;
                uint2 pb; pb.x = *(uint32_t*)&hb0; pb.y = *(uint32_t*)&hb1;
                *(uint2*)&s_h[0][nl][cq * 4] = pf;
                *(uint2*)&s_h[1][nl][cq * 4] = pb;
                *(uint2*)&s_x[nl][cq * 4]    = xrA[u];
            }
        }
    }
    __syncthreads();

    // ---- GEMM + epilogue: warps 0..3, warp = m-tile (16 nodes), both dirs ----
    if (warp < 4) {
        const int g  = lane >> 2;
        const int t  = lane & 3;
        const int m0 = warp * 16;

        float acc0[4][4], acc1[4][4];
        #pragma unroll
        for (int nt = 0; nt < 4; nt++)
            #pragma unroll
            for (int i = 0; i < 4; i++) { acc0[nt][i] = 0.f; acc1[nt][i] = 0.f; }

        #pragma unroll
        for (int kt = 0; kt < 32; kt += 16) {
            uint32_t a0 = *(const uint32_t*)&s_h[0][m0 + g    ][kt + t * 2];
            uint32_t a1 = *(const uint32_t*)&s_h[0][m0 + g + 8][kt + t * 2];
            uint32_t a2 = *(const uint32_t*)&s_h[0][m0 + g    ][kt + t * 2 + 8];
            uint32_t a3 = *(const uint32_t*)&s_h[0][m0 + g + 8][kt + t * 2 + 8];
            #pragma unroll
            for (int nt = 0; nt < 4; nt++) {
                uint32_t b0 = *(const uint32_t*)&s_wt[0][nt * 8 + g][kt + t * 2];
                uint32_t b1 = *(const uint32_t*)&s_wt[0][nt * 8 + g][kt + t * 2 + 8];
                mma_16816(acc0[nt], a0, a1, a2, a3, b0, b1);
            }
            a0 = *(const uint32_t*)&s_h[1][m0 + g    ][kt + t * 2];
            a1 = *(const uint32_t*)&s_h[1][m0 + g + 8][kt + t * 2];
            a2 = *(const uint32_t*)&s_h[1][m0 + g    ][kt + t * 2 + 8];
            a3 = *(const uint32_t*)&s_h[1][m0 + g + 8][kt + t * 2 + 8];
            #pragma unroll
            for (int nt = 0; nt < 4; nt++) {
                uint32_t b0 = *(const uint32_t*)&s_wt[1][nt * 8 + g][kt + t * 2];
                uint32_t b1 = *(const uint32_t*)&s_wt[1][nt * 8 + g][kt + t * 2 + 8];
                mma_16816(acc1[nt], a0, a1, a2, a3, b0, b1);
            }
        }

        int node0 = blockBase + m0 + g;
        int node1 = node0 + 8;
        #pragma unroll
        for (int nt = 0; nt < 4; nt++) {
            int col = nt * 8 + t * 2;
            float2 xv0 = __half22float2(*(__half2*)&s_x[m0 + g    ][col]);
            float2 xv1 = __half22float2(*(__half2*)&s_x[m0 + g + 8][col]);
            float o00 = xv0.x + fmaxf(acc0[nt][0], 0.f) + fmaxf(acc1[nt][0], 0.f);
            float o01 = xv0.y + fmaxf(acc0[nt][1], 0.f) + fmaxf(acc1[nt][1], 0.f);
            float o10 = xv1.x + fmaxf(acc0[nt][2], 0.f) + fmaxf(acc1[nt][2], 0.f);
            float o11 = xv1.y + fmaxf(acc0[nt][3], 0.f) + fmaxf(acc1[nt][3], 0.f);
            if (node0 < n)
                *(__half2*)&xout[(size_t)node0 * C + col] = __floats2half2_rn(o00, o01);
            if (node1 < n)
                *(__half2*)&xout[(size_t)node1 * C + col] = __floats2half2_rn(o10, o11);
        }
    }
}

// ---------------- pooling: per-graph sum + count (batch sorted) ----------------
__global__ void k_pool(const int* __restrict__ batch, const __half* __restrict__ x, int n)
{
    int lane = threadIdx.x & 31;
    int warp = threadIdx.x >> 5;
    int base = blockIdx.x * 256 + warp * 32;

    float acc = 0.f;
    int cur = -1, run = 0;
    for (int j = 0; j < 32; j++) {
        int node = base + j;
        if (node >= n) break;
        int b = __ldg(batch + node);
        float v = __half2float(__ldg(x + (size_t)node * C + lane));
        if (b != cur) {
            if (cur >= 0) {
                atomicAdd(&d_gsum[cur * C + lane], acc);
                if (lane == 0) atomicAdd(&d_gcnt[cur], (float)run);
            }
            cur = b; acc = 0.f; run = 0;
        }
        acc += v; run++;
    }
    if (cur >= 0) {
        atomicAdd(&d_gsum[cur * C + lane], acc);
        if (lane == 0) atomicAdd(&d_gcnt[cur], (float)run);
    }
}

// ---------------- MLP head: 8 graphs per block; self-cleans pool buffers -------
#define GPB 8
__global__ void k_mlp(const float* __restrict__ hw, const float* __restrict__ hb,
                      const float* __restrict__ ow, float* __restrict__ out)
{
    __shared__ float gs[GPB][C];
    __shared__ float sout[GPB];
    int tid = threadIdx.x;
    if (tid < GPB * C) {
        int g = tid >> 5, c = tid & 31;
        int gb = blockIdx.x * GPB + g;
        gs[g][c] = d_gsum[gb * C + c] / d_gcnt[gb];
    }
    if (tid < GPB) sout[tid] = 0.f;
    __syncthreads();
    if (tid < GPB * C) {
        int g = tid >> 5, c = tid & 31;
        d_gsum[(blockIdx.x * GPB + g) * C + c] = 0.f;
    }
    if (tid < GPB) d_gcnt[blockIdx.x * GPB + tid] = 0.f;

    float part[GPB];
    #pragma unroll
    for (int g = 0; g < GPB; g++) part[g] = 0.f;

    for (int j = tid; j < HIDDEN; j += 256) {
        float h[GPB];
        float bj = __ldg(hb + j);
        #pragma unroll
        for (int g = 0; g < GPB; g++) h[g] = bj;
        #pragma unroll
        for (int k = 0; k < C; k++) {
            float wkj = __ldg(hw + k * HIDDEN + j);
            #pragma unroll
            for (int g = 0; g < GPB; g++)
                h[g] = fmaf(gs[g][k], wkj, h[g]);
        }
        float oj = __ldg(ow + j);
        #pragma unroll
        for (int g = 0; g < GPB; g++)
            part[g] += fmaxf(h[g], 0.f) * oj;
    }
    #pragma unroll
    for (int g = 0; g < GPB; g++) {
        float v = part[g];
        #pragma unroll
        for (int off = 16; off > 0; off >>= 1)
            v += __shfl_down_sync(0xffffffffu, v, off);
        if ((tid & 31) == 0) atomicAdd(&sout[g], v);
    }
    __syncthreads();
    if (tid < GPB) out[blockIdx.x * GPB + tid] = sout[tid];
}

// ---------------- launch ---------------------------------------------------------
extern "C" void kernel_launch(void* const* d_in, const int* in_sizes, int n_in,
                              void* d_out, int out_size)
{
    const int*   nodes    = (const int*)  d_in[0];
    const int*   sources  = (const int*)  d_in[1];
    const int*   targets  = (const int*)  d_in[2];
    const int*   batch    = (const int*)  d_in[3];
    const float* emb      = (const float*)d_in[4];
    const float* conv_w   = (const float*)d_in[5];
    const float* hidden_w = (const float*)d_in[6];
    const float* hidden_b = (const float*)d_in[7];
    const float* out_w    = (const float*)d_in[8];
    float*       out      = (float*)d_out;

    const int N = in_sizes[0];
    const int E = in_sizes[1];

    // CSR build: hist (+flag reset), single-pass scan, scatter+init
    k_hist        <<<(E + 255) / 256, 256>>>(sources, targets, E);
    k_scan        <<<dim3(NBLK, 2), SCAN_BLK>>>();
    k_scatter_init<<<(N * C + 255) / 256, 256>>>(sources, targets, nodes, emb, E, N);

    // 8 fused layers, ping-pong (even count -> final in buffer 0)
    const int nb = (N + 63) / 64;
    __half* xh = nullptr;
    cudaGetSymbolAddress((void**)&xh, d_xh);
    __half* xa = xh;
    __half* xb = xh + (size_t)N_NODES * C;
    for (int l = 0; l < LAYERS; l++) {
        const float* wl = conv_w + (size_t)l * 2 * C * C;
        if ((l & 1) == 0) k_layer<<<nb, 256>>>(xa, xb, wl, N);
        else              k_layer<<<nb, 256>>>(xb, xa, wl, N);
    }
    k_pool<<<(N + 255) / 256, 256>>>(batch, xa, N);

    k_mlp<<<NGRAPH / GPB, 256>>>(hidden_w, hidden_b, out_w, out);
}

// round 14
// speedup vs baseline: 1.4830x; 1.1429x over previous
#include <cuda_runtime.h>
#include <cuda_fp16.h>
#include <cstdint>

#define N_NODES 500000
#define N_EDGES 2000000
#define C       32
#define NGRAPH  1024
#define HIDDEN  1024
#define LAYERS  8

#define SCAN_BLK 256
#define ITEMS    8
#define CHUNK    (SCAN_BLK * ITEMS)                       // 2048
#define NBLK     ((N_NODES + CHUNK - 1) / CHUNK)          // 245

// ---------------- device scratch (static; zero-initialized at load) ----------
__device__ __half d_xh  [2][(size_t)N_NODES * C];         // fp16 feature ping/pong
__device__ int    d_cnt [2][N_NODES];                     // degrees (self-cleaned by k_scan)
__device__ int    d_cur [2][N_NODES];                     // scatter cursors
__device__ int    d_csr [2][N_EDGES];
__device__ int4   d_meta[N_NODES];                        // {b0, d0, b1, d1}
__device__ int    d_agg [2][NBLK];                        // scan block aggregates
__device__ int    d_flag[2][NBLK];                        // publish flags (reset by k_hist)
__device__ float  d_gsum[NGRAPH * C];                     // self-cleaned by k_mlp
__device__ float  d_gcnt[NGRAPH];

// ---------------- degree histogram + scan-flag reset ---------------------------
__global__ void k_hist(const int* __restrict__ src, const int* __restrict__ dst, int E)
{
    int e = blockIdx.x * blockDim.x + threadIdx.x;
    if (e < 2 * NBLK) ((int*)d_flag)[e] = 0;    // reset flags for this call's k_scan
    if (e >= E) return;
    atomicAdd(&d_cnt[0][__ldg(dst + e)], 1);
    atomicAdd(&d_cnt[1][__ldg(src + e)], 1);
}

// ---------------- single-pass scan: publish aggregate, lookback, write meta ----
__global__ void k_scan()
{
    int y   = blockIdx.y;
    int bid = blockIdx.x;
    int tid = threadIdx.x;
    int lane = tid & 31, warp = tid >> 5;
    int base_i = bid * CHUNK + tid * ITEMS;

    int v[ITEMS]; int tsum = 0;
    #pragma unroll
    for (int j = 0; j < ITEMS; j++) {
        int i = base_i + j;
        v[j] = (i < N_NODES) ? d_cnt[y][i] : 0;
        tsum += v[j];
    }
    int incl = tsum;
    #pragma unroll
    for (int o = 1; o < 32; o <<= 1) {
        int t = __shfl_up_sync(0xffffffffu, incl, o);
        if (lane >= o) incl += t;
    }
    __shared__ int shw[8];
    __shared__ int s_tot;
    if (lane == 31) shw[warp] = incl;
    __syncthreads();
    if (warp == 0 && lane < 8) {
        int b = shw[lane], ib = b;
        #pragma unroll
        for (int o = 1; o < 8; o <<= 1) {
            int t = __shfl_up_sync(0xffu, ib, o);
            if (lane >= o) ib += t;
        }
        shw[lane] = ib - b;                     // exclusive warp base
        if (lane == 7) s_tot = ib;              // block total
    }
    __syncthreads();

    if (tid == 0) {
        d_agg[y][bid] = s_tot;
        __threadfence();
        d_flag[y][bid] = 1;
    }

    __shared__ int s_red[SCAN_BLK];
    int a = 0;
    if (tid < bid) {
        volatile int* fl = &d_flag[y][0];
        while (fl[tid] == 0) { }
        __threadfence();
        a = *((volatile int*)&d_agg[y][tid]);
    }
    s_red[tid] = a;
    __syncthreads();
    #pragma unroll
    for (int o = SCAN_BLK / 2; o > 0; o >>= 1) {
        if (tid < o) s_red[tid] += s_red[tid + o];
        __syncthreads();
    }
    int run = s_red[0] + shw[warp] + (incl - tsum);

    #pragma unroll
    for (int j = 0; j < ITEMS; j++) {
        int i = base_i + j;
        if (i < N_NODES) {
            int* mp = (int*)&d_meta[i];
            mp[y * 2 + 0] = run;          // base
            mp[y * 2 + 1] = v[j];         // degree
            d_cur[y][i]   = run;
            d_cnt[y][i]   = 0;            // self-clean for next call
            run += v[j];
        }
    }
}

// ---------------- fused CSR fill + feature init --------------------------------
__global__ void k_scatter_init(const int* __restrict__ src, const int* __restrict__ dst,
                               const int* __restrict__ nodes, const float* __restrict__ emb,
                               int E, int n)
{
    int idx = blockIdx.x * blockDim.x + threadIdx.x;
    if (idx < n * C) {
        int node = idx >> 5;
        int c    = idx & 31;
        int t    = __ldg(nodes + node);
        d_xh[0][idx] = __float2half_rn(__ldg(emb + t * C + c));
    }
    if (idx < E) {
        int s = __ldg(src + idx);
        int t = __ldg(dst + idx);
        int p = atomicAdd(&d_cur[0][t], 1);  d_csr[0][p] = s;
        int q = atomicAdd(&d_cur[1][s], 1);  d_csr[1][q] = t;
    }
}

// ---------------- mma.m16n8k16 helper -------------------------------------------
__device__ __forceinline__ void mma_16816(float* d,
                                          uint32_t a0, uint32_t a1, uint32_t a2, uint32_t a3,
                                          uint32_t b0, uint32_t b1)
{
    asm volatile(
        "mma.sync.aligned.m16n8k16.row.col.f32.f16.f16.f32 "
        "{%0,%1,%2,%3}, {%4,%5,%6,%7}, {%8,%9}, {%0,%1,%2,%3};"
        : "+f"(d[0]), "+f"(d[1]), "+f"(d[2]), "+f"(d[3])
        : "r"(a0), "r"(a1), "r"(a2), "r"(a3), "r"(b0), "r"(b1));
}

// ---------------- fused layer: node-quad gather (no reduction) -> mma ----------
// 256 threads = 8 warps; 64 nodes/block. Gather: lane = (q = lane>>3 node-in-quad,
// cq = lane&7 channel quad). One LDG fetches one neighbor row for each of 4
// nodes; each node's sum accumulates in its own 8 lanes in fp32 — no shfl
// reduction, no tail path (warp-uniform loop to max degree).
#define CAPI 512
__global__ void __launch_bounds__(256) k_layer(const __half* __restrict__ xin,
                                               __half* __restrict__ xout,
                                               const float* __restrict__ w, int n)
{
    __shared__ __half s_wt[2][32][32];   // 4 KB transposed weights
    __shared__ __half s_h [2][64][32];   // 8 KB aggregated features
    __shared__ __half s_x [64][32];      // 4 KB residual (block-staged)
    __shared__ int4   s_meta[64];        // 1 KB node meta
    __shared__ int    s_idx[2][CAPI];    // 4 KB CSR slices

    const int tid  = threadIdx.x;
    const int lane = tid & 31;
    const int warp = tid >> 5;
    const int q    = lane >> 3;           // node in quad 0..3
    const int cq   = lane & 7;            // channel quad (4 halves = 8 B)
    const int blockBase = blockIdx.x * 64;
    const int lastLocal = min(64, n - blockBase);
    const unsigned FULL = 0xffffffffu;

    // stage weights (transposed)
    for (int i = tid; i < 2 * 32 * 32; i += 256) {
        int d = i >> 10, rem = i & 1023, k = rem >> 5, j = rem & 31;
        s_wt[d][j][k] = __float2half_rn(__ldg(w + d * 1024 + k * 32 + j));
    }
    // stage meta
    if (tid < 64) {
        s_meta[tid] = (tid < lastLocal) ? __ldg(&d_meta[blockBase + tid])
                                        : make_int4(0, 0, 0, 0);
    }
    // stage residual rows: 64 rows x 64 B = 4 KB, one uint4 per thread (coalesced)
    {
        int i = tid * 8;                              // halves
        uint4 val = make_uint4(0u, 0u, 0u, 0u);
        if (i < lastLocal * C)
            val = *(const uint4*)(xin + (size_t)blockBase * C + i);
        *(uint4*)&(((__half*)s_x)[i]) = val;
    }
    __syncthreads();

    // stage contiguous CSR slices
    const int4 mF = s_meta[0];
    const int4 mL = s_meta[lastLocal - 1];
    const int beg0 = mF.x, len0 = mL.x + mL.y - mF.x;
    const int beg1 = mF.z, len1 = mL.z + mL.w - mF.z;
    for (int i = tid; i < min(len0, CAPI); i += 256) s_idx[0][i] = __ldg(&d_csr[0][beg0 + i]);
    for (int i = tid; i < min(len1, CAPI); i += 256) s_idx[1][i] = __ldg(&d_csr[1][beg1 + i]);
    __syncthreads();

    // ---- gather: 2 passes of 4 nodes per warp ----
    #pragma unroll
    for (int pass = 0; pass < 2; pass++) {
        const int nl = warp * 8 + pass * 4 + q;
        const int4 m = s_meta[nl];
        const int o0 = m.x - beg0, dg0 = m.y;
        const int o1 = m.z - beg1, dg1 = m.w;

        // seed with residual (from smem)
        uint2 xr = *(const uint2*)&s_x[nl][cq * 4];
        float2 xa = __half22float2(*(__half2*)&xr.x);
        float2 xb = __half22float2(*(__half2*)&xr.y);
        float f0 = xa.x, f1 = xa.y, f2 = xb.x, f3 = xb.y;
        float g0 = xa.x, g1 = xa.y, g2 = xb.x, g3 = xb.y;

        const int jm = max(__reduce_max_sync(FULL, (unsigned)dg0),
                           __reduce_max_sync(FULL, (unsigned)dg1));

        int j = 0;
        // unrolled-by-2 main loop: 4 independent LDGs in flight
        for (; j + 2 <= jm; j += 2) {
            uint2 v0a = make_uint2(0u, 0u), v1a = make_uint2(0u, 0u);
            uint2 v0b = make_uint2(0u, 0u), v1b = make_uint2(0u, 0u);
            if (j < dg0) {
                int p = o0 + j;
                int s = (p < CAPI) ? s_idx[0][p] : __ldg(&d_csr[0][beg0 + p]);
                v0a = __ldg((const uint2*)(xin + (size_t)s * C) + cq);
            }
            if (j + 1 < dg0) {
                int p = o0 + j + 1;
                int s = (p < CAPI) ? s_idx[0][p] : __ldg(&d_csr[0][beg0 + p]);
                v0b = __ldg((const uint2*)(xin + (size_t)s * C) + cq);
            }
            if (j < dg1) {
                int p = o1 + j;
                int s = (p < CAPI) ? s_idx[1][p] : __ldg(&d_csr[1][beg1 + p]);
                v1a = __ldg((const uint2*)(xin + (size_t)s * C) + cq);
            }
            if (j + 1 < dg1) {
                int p = o1 + j + 1;
                int s = (p < CAPI) ? s_idx[1][p] : __ldg(&d_csr[1][beg1 + p]);
                v1b = __ldg((const uint2*)(xin + (size_t)s * C) + cq);
            }
            float2 t0, t1;
            t0 = __half22float2(*(__half2*)&v0a.x); t1 = __half22float2(*(__half2*)&v0a.y);
            f0 += t0.x; f1 += t0.y; f2 += t1.x; f3 += t1.y;
            t0 = __half22float2(*(__half2*)&v0b.x); t1 = __half22float2(*(__half2*)&v0b.y);
            f0 += t0.x; f1 += t0.y; f2 += t1.x; f3 += t1.y;
            t0 = __half22float2(*(__half2*)&v1a.x); t1 = __half22float2(*(__half2*)&v1a.y);
            g0 += t0.x; g1 += t0.y; g2 += t1.x; g3 += t1.y;
            t0 = __half22float2(*(__half2*)&v1b.x); t1 = __half22float2(*(__half2*)&v1b.y);
            g0 += t0.x; g1 += t0.y; g2 += t1.x; g3 += t1.y;
        }
        if (j < jm) {
            uint2 v0 = make_uint2(0u, 0u), v1 = make_uint2(0u, 0u);
            if (j < dg0) {
                int p = o0 + j;
                int s = (p < CAPI) ? s_idx[0][p] : __ldg(&d_csr[0][beg0 + p]);
                v0 = __ldg((const uint2*)(xin + (size_t)s * C) + cq);
            }
            if (j < dg1) {
                int p = o1 + j;
                int s = (p < CAPI) ? s_idx[1][p] : __ldg(&d_csr[1][beg1 + p]);
                v1 = __ldg((const uint2*)(xin + (size_t)s * C) + cq);
            }
            float2 t0, t1;
            t0 = __half22float2(*(__half2*)&v0.x); t1 = __half22float2(*(__half2*)&v0.y);
            f0 += t0.x; f1 += t0.y; f2 += t1.x; f3 += t1.y;
            t0 = __half22float2(*(__half2*)&v1.x); t1 = __half22float2(*(__half2*)&v1.y);
            g0 += t0.x; g1 += t0.y; g2 += t1.x; g3 += t1.y;
        }

        const float nf = __fdividef(1.f, 1.f + (float)dg0);
        const float nb = __fdividef(1.f, 1.f + (float)dg1);

        __half2 hf0 = __floats2half2_rn(f0 * nf, f1 * nf);
        __half2 hf1 = __floats2half2_rn(f2 * nf, f3 * nf);
        __half2 hb0 = __floats2half2_rn(g0 * nb, g1 * nb);
        __half2 hb1 = __floats2half2_rn(g2 * nb, g3 * nb);
        uint2 pf; pf.x = *(uint32_t*)&hf0; pf.y = *(uint32_t*)&hf1;
        uint2 pb; pb.x = *(uint32_t*)&hb0; pb.y = *(uint32_t*)&hb1;
        *(uint2*)&s_h[0][nl][cq * 4] = pf;     // every lane owns distinct 4 channels
        *(uint2*)&s_h[1][nl][cq * 4] = pb;
    }
    __syncthreads();

    // ---- GEMM + epilogue: warps 0..3, warp = m-tile (16 nodes), both dirs ----
    if (warp < 4) {
        const int g  = lane >> 2;
        const int t  = lane & 3;
        const int m0 = warp * 16;

        float acc0[4][4], acc1[4][4];
        #pragma unroll
        for (int nt = 0; nt < 4; nt++)
            #pragma unroll
            for (int i = 0; i < 4; i++) { acc0[nt][i] = 0.f; acc1[nt][i] = 0.f; }

        #pragma unroll
        for (int kt = 0; kt < 32; kt += 16) {
            uint32_t a0 = *(const uint32_t*)&s_h[0][m0 + g    ][kt + t * 2];
            uint32_t a1 = *(const uint32_t*)&s_h[0][m0 + g + 8][kt + t * 2];
            uint32_t a2 = *(const uint32_t*)&s_h[0][m0 + g    ][kt + t * 2 + 8];
            uint32_t a3 = *(const uint32_t*)&s_h[0][m0 + g + 8][kt + t * 2 + 8];
            #pragma unroll
            for (int nt = 0; nt < 4; nt++) {
                uint32_t b0 = *(const uint32_t*)&s_wt[0][nt * 8 + g][kt + t * 2];
                uint32_t b1 = *(const uint32_t*)&s_wt[0][nt * 8 + g][kt + t * 2 + 8];
                mma_16816(acc0[nt], a0, a1, a2, a3, b0, b1);
            }
            a0 = *(const uint32_t*)&s_h[1][m0 + g    ][kt + t * 2];
            a1 = *(const uint32_t*)&s_h[1][m0 + g + 8][kt + t * 2];
            a2 = *(const uint32_t*)&s_h[1][m0 + g    ][kt + t * 2 + 8];
            a3 = *(const uint32_t*)&s_h[1][m0 + g + 8][kt + t * 2 + 8];
            #pragma unroll
            for (int nt = 0; nt < 4; nt++) {
                uint32_t b0 = *(const uint32_t*)&s_wt[1][nt * 8 + g][kt + t * 2];
                uint32_t b1 = *(const uint32_t*)&s_wt[1][nt * 8 + g][kt + t * 2 + 8];
                mma_16816(acc1[nt], a0, a1, a2, a3, b0, b1);
            }
        }

        int node0 = blockBase + m0 + g;
        int node1 = node0 + 8;
        #pragma unroll
        for (int nt = 0; nt < 4; nt++) {
            int col = nt * 8 + t * 2;
            float2 xv0 = __half22float2(*(__half2*)&s_x[m0 + g    ][col]);
            float2 xv1 = __half22float2(*(__half2*)&s_x[m0 + g + 8][col]);
            float o00 = xv0.x + fmaxf(acc0[nt][0], 0.f) + fmaxf(acc1[nt][0], 0.f);
            float o01 = xv0.y + fmaxf(acc0[nt][1], 0.f) + fmaxf(acc1[nt][1], 0.f);
            float o10 = xv1.x + fmaxf(acc0[nt][2], 0.f) + fmaxf(acc1[nt][2], 0.f);
            float o11 = xv1.y + fmaxf(acc0[nt][3], 0.f) + fmaxf(acc1[nt][3], 0.f);
            if (node0 < n)
                *(__half2*)&xout[(size_t)node0 * C + col] = __floats2half2_rn(o00, o01);
            if (node1 < n)
                *(__half2*)&xout[(size_t)node1 * C + col] = __floats2half2_rn(o10, o11);
        }
    }
}

// ---------------- pooling: per-graph sum + count (batch sorted) ----------------
__global__ void k_pool(const int* __restrict__ batch, const __half* __restrict__ x, int n)
{
    int lane = threadIdx.x & 31;
    int warp = threadIdx.x >> 5;
    int base = blockIdx.x * 256 + warp * 32;

    float acc = 0.f;
    int cur = -1, run = 0;
    for (int j = 0; j < 32; j++) {
        int node = base + j;
        if (node >= n) break;
        int b = __ldg(batch + node);
        float v = __half2float(__ldg(x + (size_t)node * C + lane));
        if (b != cur) {
            if (cur >= 0) {
                atomicAdd(&d_gsum[cur * C + lane], acc);
                if (lane == 0) atomicAdd(&d_gcnt[cur], (float)run);
            }
            cur = b; acc = 0.f; run = 0;
        }
        acc += v; run++;
    }
    if (cur >= 0) {
        atomicAdd(&d_gsum[cur * C + lane], acc);
        if (lane == 0) atomicAdd(&d_gcnt[cur], (float)run);
    }
}

// ---------------- MLP head: 8 graphs per block; self-cleans pool buffers -------
#define GPB 8
__global__ void k_mlp(const float* __restrict__ hw, const float* __restrict__ hb,
                      const float* __restrict__ ow, float* __restrict__ out)
{
    __shared__ float gs[GPB][C];
    __shared__ float sout[GPB];
    int tid = threadIdx.x;
    if (tid < GPB * C) {
        int g = tid >> 5, c = tid & 31;
        int gb = blockIdx.x * GPB + g;
        gs[g][c] = d_gsum[gb * C + c] / d_gcnt[gb];
    }
    if (tid < GPB) sout[tid] = 0.f;
    __syncthreads();
    if (tid < GPB * C) {
        int g = tid >> 5, c = tid & 31;
        d_gsum[(blockIdx.x * GPB + g) * C + c] = 0.f;
    }
    if (tid < GPB) d_gcnt[blockIdx.x * GPB + tid] = 0.f;

    float part[GPB];
    #pragma unroll
    for (int g = 0; g < GPB; g++) part[g] = 0.f;

    for (int j = tid; j < HIDDEN; j += 256) {
        float h[GPB];
        float bj = __ldg(hb + j);
        #pragma unroll
        for (int g = 0; g < GPB; g++) h[g] = bj;
        #pragma unroll
        for (int k = 0; k < C; k++) {
            float wkj = __ldg(hw + k * HIDDEN + j);
            #pragma unroll
            for (int g = 0; g < GPB; g++)
                h[g] = fmaf(gs[g][k], wkj, h[g]);
        }
        float oj = __ldg(ow + j);
        #pragma unroll
        for (int g = 0; g < GPB; g++)
            part[g] += fmaxf(h[g], 0.f) * oj;
    }
    #pragma unroll
    for (int g = 0; g < GPB; g++) {
        float v = part[g];
        #pragma unroll
        for (int off = 16; off > 0; off >>= 1)
            v += __shfl_down_sync(0xffffffffu, v, off);
        if ((tid & 31) == 0) atomicAdd(&sout[g], v);
    }
    __syncthreads();
    if (tid < GPB) out[blockIdx.x * GPB + tid] = sout[tid];
}

// ---------------- launch ---------------------------------------------------------
extern "C" void kernel_launch(void* const* d_in, const int* in_sizes, int n_in,
                              void* d_out, int out_size)
{
    const int*   nodes    = (const int*)  d_in[0];
    const int*   sources  = (const int*)  d_in[1];
    const int*   targets  = (const int*)  d_in[2];
    const int*   batch    = (const int*)  d_in[3];
    const float* emb      = (const float*)d_in[4];
    const float* conv_w   = (const float*)d_in[5];
    const float* hidden_w = (const float*)d_in[6];
    const float* hidden_b = (const float*)d_in[7];
    const float* out_w    = (const float*)d_in[8];
    float*       out      = (float*)d_out;

    const int N = in_sizes[0];
    const int E = in_sizes[1];

    // CSR build: hist (+flag reset), single-pass scan, scatter+init
    k_hist        <<<(E + 255) / 256, 256>>>(sources, targets, E);
    k_scan        <<<dim3(NBLK, 2), SCAN_BLK>>>();
    k_scatter_init<<<(N * C + 255) / 256, 256>>>(sources, targets, nodes, emb, E, N);

    // 8 fused layers, ping-pong (even count -> final in buffer 0)
    const int nb = (N + 63) / 64;
    __half* xh = nullptr;
    cudaGetSymbolAddress((void**)&xh, d_xh);
    __half* xa = xh;
    __half* xb = xh + (size_t)N_NODES * C;
    for (int l = 0; l < LAYERS; l++) {
        const float* wl = conv_w + (size_t)l * 2 * C * C;
        if ((l & 1) == 0) k_layer<<<nb, 256>>>(xa, xb, wl, N);
        else              k_layer<<<nb, 256>>>(xb, xa, wl, N);
    }
    k_pool<<<(N + 255) / 256, 256>>>(batch, xa, N);

    k_mlp<<<NGRAPH / GPB, 256>>>(hidden_w, hidden_b, out_w, out);
}

// round 15
// speedup vs baseline: 1.9045x; 1.2842x over previous
#include <cuda_runtime.h>
#include <cuda_fp16.h>
#include <cstdint>

#define N_NODES 500000
#define N_EDGES 2000000
#define C       32
#define NGRAPH  1024
#define HIDDEN  1024
#define LAYERS  8

#define SCAN_BLK 256
#define ITEMS    8
#define CHUNK    (SCAN_BLK * ITEMS)                       // 2048
#define NBLK     ((N_NODES + CHUNK - 1) / CHUNK)          // 245

// ---------------- device scratch (static; zero-initialized at load) ----------
__device__ __half d_xh  [2][(size_t)N_NODES * C];         // fp16 feature ping/pong
__device__ int    d_cnt [2][N_NODES];                     // degrees (self-cleaned by k_scan)
__device__ int    d_cur [2][N_NODES];                     // scatter cursors
__device__ int    d_csr [2][N_EDGES];
__device__ int4   d_meta[N_NODES];                        // {b0, d0, b1, d1}
__device__ int    d_agg [2][NBLK];                        // scan block aggregates
__device__ int    d_flag[2][NBLK];                        // publish flags (reset by k_hist)
__device__ float  d_gsum[NGRAPH * C];                     // self-cleaned by k_mlp
__device__ float  d_gcnt[NGRAPH];

// ---------------- degree histogram + scan-flag reset ---------------------------
__global__ void k_hist(const int* __restrict__ src, const int* __restrict__ dst, int E)
{
    int e = blockIdx.x * blockDim.x + threadIdx.x;
    if (e < 2 * NBLK) ((int*)d_flag)[e] = 0;    // reset flags for this call's k_scan
    if (e >= E) return;
    atomicAdd(&d_cnt[0][__ldg(dst + e)], 1);
    atomicAdd(&d_cnt[1][__ldg(src + e)], 1);
}

// ---------------- single-pass scan: publish aggregate, lookback, write meta ----
__global__ void k_scan()
{
    int y   = blockIdx.y;
    int bid = blockIdx.x;
    int tid = threadIdx.x;
    int lane = tid & 31, warp = tid >> 5;
    int base_i = bid * CHUNK + tid * ITEMS;

    int v[ITEMS]; int tsum = 0;
    #pragma unroll
    for (int j = 0; j < ITEMS; j++) {
        int i = base_i + j;
        v[j] = (i < N_NODES) ? d_cnt[y][i] : 0;
        tsum += v[j];
    }
    int incl = tsum;
    #pragma unroll
    for (int o = 1; o < 32; o <<= 1) {
        int t = __shfl_up_sync(0xffffffffu, incl, o);
        if (lane >= o) incl += t;
    }
    __shared__ int shw[8];
    __shared__ int s_tot;
    if (lane == 31) shw[warp] = incl;
    __syncthreads();
    if (warp == 0 && lane < 8) {
        int b = shw[lane], ib = b;
        #pragma unroll
        for (int o = 1; o < 8; o <<= 1) {
            int t = __shfl_up_sync(0xffu, ib, o);
            if (lane >= o) ib += t;
        }
        shw[lane] = ib - b;                     // exclusive warp base
        if (lane == 7) s_tot = ib;              // block total
    }
    __syncthreads();

    if (tid == 0) {
        d_agg[y][bid] = s_tot;
        __threadfence();
        d_flag[y][bid] = 1;
    }

    __shared__ int s_red[SCAN_BLK];
    int a = 0;
    if (tid < bid) {
        volatile int* fl = &d_flag[y][0];
        while (fl[tid] == 0) { }
        __threadfence();
        a = *((volatile int*)&d_agg[y][tid]);
    }
    s_red[tid] = a;
    __syncthreads();
    #pragma unroll
    for (int o = SCAN_BLK / 2; o > 0; o >>= 1) {
        if (tid < o) s_red[tid] += s_red[tid + o];
        __syncthreads();
    }
    int run = s_red[0] + shw[warp] + (incl - tsum);

    #pragma unroll
    for (int j = 0; j < ITEMS; j++) {
        int i = base_i + j;
        if (i < N_NODES) {
            int* mp = (int*)&d_meta[i];
            mp[y * 2 + 0] = run;          // base
            mp[y * 2 + 1] = v[j];         // degree
            d_cur[y][i]   = run;
            d_cnt[y][i]   = 0;            // self-clean for next call
            run += v[j];
        }
    }
}

// ---------------- fused CSR fill + feature init --------------------------------
__global__ void k_scatter_init(const int* __restrict__ src, const int* __restrict__ dst,
                               const int* __restrict__ nodes, const float* __restrict__ emb,
                               int E, int n)
{
    int idx = blockIdx.x * blockDim.x + threadIdx.x;
    if (idx < n * C) {
        int node = idx >> 5;
        int c    = idx & 31;
        int t    = __ldg(nodes + node);
        d_xh[0][idx] = __float2half_rn(__ldg(emb + t * C + c));
    }
    if (idx < E) {
        int s = __ldg(src + idx);
        int t = __ldg(dst + idx);
        int p = atomicAdd(&d_cur[0][t], 1);  d_csr[0][p] = s;
        int q = atomicAdd(&d_cur[1][s], 1);  d_csr[1][q] = t;
    }
}

// ---------------- mma.m16n8k16 helper -------------------------------------------
__device__ __forceinline__ void mma_16816(float* d,
                                          uint32_t a0, uint32_t a1, uint32_t a2, uint32_t a3,
                                          uint32_t b0, uint32_t b1)
{
    asm volatile(
        "mma.sync.aligned.m16n8k16.row.col.f32.f16.f16.f32 "
        "{%0,%1,%2,%3}, {%4,%5,%6,%7}, {%8,%9}, {%0,%1,%2,%3};"
        : "+f"(d[0]), "+f"(d[1]), "+f"(d[2]), "+f"(d[3])
        : "r"(a0), "r"(a1), "r"(a2), "r"(a3), "r"(b0), "r"(b1));
}

#define CAPI 512

// ---- gather pass: FAST = CSR slice fully staged in smem (no bounds check) -----
template<bool FAST>
__device__ __forceinline__ void gather_pass(
    int nl, const __half* __restrict__ xin,
    const int4* s_meta, int beg0, int beg1, const int (*s_idx)[CAPI],
    int cq, const __half (*s_x)[32],
    __half (*s_h0)[32], __half (*s_h1)[32])
{
    const unsigned FULL = 0xffffffffu;
    const int4 m = s_meta[nl];
    const int o0 = m.x - beg0, dg0 = m.y;
    const int o1 = m.z - beg1, dg1 = m.w;

    // seed with residual (from smem)
    uint2 xr = *(const uint2*)&s_x[nl][cq * 4];
    float2 xa = __half22float2(*(__half2*)&xr.x);
    float2 xb = __half22float2(*(__half2*)&xr.y);
    float f0 = xa.x, f1 = xa.y, f2 = xb.x, f3 = xb.y;
    float g0 = xa.x, g1 = xa.y, g2 = xb.x, g3 = xb.y;

    const int jm = max(__reduce_max_sync(FULL, (unsigned)dg0),
                       __reduce_max_sync(FULL, (unsigned)dg1));

    int j = 0;
    for (; j + 2 <= jm; j += 2) {
        uint2 v0a = make_uint2(0u, 0u), v1a = make_uint2(0u, 0u);
        uint2 v0b = make_uint2(0u, 0u), v1b = make_uint2(0u, 0u);
        if (j < dg0) {
            int p = o0 + j;
            int s = FAST ? s_idx[0][p] : ((p < CAPI) ? s_idx[0][p] : __ldg(&d_csr[0][beg0 + p]));
            v0a = __ldg((const uint2*)(xin + (size_t)s * C) + cq);
        }
        if (j + 1 < dg0) {
            int p = o0 + j + 1;
            int s = FAST ? s_idx[0][p] : ((p < CAPI) ? s_idx[0][p] : __ldg(&d_csr[0][beg0 + p]));
            v0b = __ldg((const uint2*)(xin + (size_t)s * C) + cq);
        }
        if (j < dg1) {
            int p = o1 + j;
            int s = FAST ? s_idx[1][p] : ((p < CAPI) ? s_idx[1][p] : __ldg(&d_csr[1][beg1 + p]));
            v1a = __ldg((const uint2*)(xin + (size_t)s * C) + cq);
        }
        if (j + 1 < dg1) {
            int p = o1 + j + 1;
            int s = FAST ? s_idx[1][p] : ((p < CAPI) ? s_idx[1][p] : __ldg(&d_csr[1][beg1 + p]));
            v1b = __ldg((const uint2*)(xin + (size_t)s * C) + cq);
        }
        // pairwise fp16 add (one rounding per value), single convert, fp32 accumulate
        __half2 pa = __hadd2(*(__half2*)&v0a.x, *(__half2*)&v0b.x);
        __half2 pb = __hadd2(*(__half2*)&v0a.y, *(__half2*)&v0b.y);
        float2 t = __half22float2(pa); f0 += t.x; f1 += t.y;
        t = __half22float2(pb);        f2 += t.x; f3 += t.y;
        pa = __hadd2(*(__half2*)&v1a.x, *(__half2*)&v1b.x);
        pb = __hadd2(*(__half2*)&v1a.y, *(__half2*)&v1b.y);
        t = __half22float2(pa);        g0 += t.x; g1 += t.y;
        t = __half22float2(pb);        g2 += t.x; g3 += t.y;
    }
    if (j < jm) {
        uint2 v0 = make_uint2(0u, 0u), v1 = make_uint2(0u, 0u);
        if (j < dg0) {
            int p = o0 + j;
            int s = FAST ? s_idx[0][p] : ((p < CAPI) ? s_idx[0][p] : __ldg(&d_csr[0][beg0 + p]));
            v0 = __ldg((const uint2*)(xin + (size_t)s * C) + cq);
        }
        if (j < dg1) {
            int p = o1 + j;
            int s = FAST ? s_idx[1][p] : ((p < CAPI) ? s_idx[1][p] : __ldg(&d_csr[1][beg1 + p]));
            v1 = __ldg((const uint2*)(xin + (size_t)s * C) + cq);
        }
        float2 t0, t1;
        t0 = __half22float2(*(__half2*)&v0.x); t1 = __half22float2(*(__half2*)&v0.y);
        f0 += t0.x; f1 += t0.y; f2 += t1.x; f3 += t1.y;
        t0 = __half22float2(*(__half2*)&v1.x); t1 = __half22float2(*(__half2*)&v1.y);
        g0 += t0.x; g1 += t0.y; g2 += t1.x; g3 += t1.y;
    }

    const float nf = __fdividef(1.f, 1.f + (float)dg0);
    const float nb = __fdividef(1.f, 1.f + (float)dg1);

    __half2 hf0 = __floats2half2_rn(f0 * nf, f1 * nf);
    __half2 hf1 = __floats2half2_rn(f2 * nf, f3 * nf);
    __half2 hb0 = __floats2half2_rn(g0 * nb, g1 * nb);
    __half2 hb1 = __floats2half2_rn(g2 * nb, g3 * nb);
    uint2 pf; pf.x = *(uint32_t*)&hf0; pf.y = *(uint32_t*)&hf1;
    uint2 pb2; pb2.x = *(uint32_t*)&hb0; pb2.y = *(uint32_t*)&hb1;
    *(uint2*)&s_h0[nl][cq * 4] = pf;
    *(uint2*)&s_h1[nl][cq * 4] = pb2;
}

// ---------------- fused layer: node-quad gather (no reduction) -> mma ----------
// 256 threads = 8 warps; 64 nodes/block. lane = (q = lane>>3 node-in-quad,
// cq = lane&7 channel quad). fp32 per-node accumulators in own lanes; pairwise
// HADD2 pre-sum; block-uniform fast path when CSR slices fit smem.
__global__ void __launch_bounds__(256) k_layer(const __half* __restrict__ xin,
                                               __half* __restrict__ xout,
                                               const float* __restrict__ w, int n)
{
    __shared__ __half s_wt[2][32][32];   // 4 KB transposed weights
    __shared__ __half s_h [2][64][32];   // 8 KB aggregated features
    __shared__ __half s_x [64][32];      // 4 KB residual (block-staged)
    __shared__ int4   s_meta[64];        // 1 KB node meta
    __shared__ int    s_idx[2][CAPI];    // 4 KB CSR slices

    const int tid  = threadIdx.x;
    const int lane = tid & 31;
    const int warp = tid >> 5;
    const int q    = lane >> 3;           // node in quad 0..3
    const int cq   = lane & 7;            // channel quad (4 halves = 8 B)
    const int blockBase = blockIdx.x * 64;
    const int lastLocal = min(64, n - blockBase);

    for (int i = tid; i < 2 * 32 * 32; i += 256) {
        int d = i >> 10, rem = i & 1023, k = rem >> 5, j = rem & 31;
        s_wt[d][j][k] = __float2half_rn(__ldg(w + d * 1024 + k * 32 + j));
    }
    if (tid < 64) {
        s_meta[tid] = (tid < lastLocal) ? __ldg(&d_meta[blockBase + tid])
                                        : make_int4(0, 0, 0, 0);
    }
    // stage residual rows: 64 rows x 64 B = 4 KB, one uint4 per thread (coalesced)
    {
        int i = tid * 8;                              // halves
        uint4 val = make_uint4(0u, 0u, 0u, 0u);
        if (i < lastLocal * C)
            val = *(const uint4*)(xin + (size_t)blockBase * C + i);
        *(uint4*)&(((__half*)s_x)[i]) = val;
    }
    __syncthreads();

    const int4 mF = s_meta[0];
    const int4 mL = s_meta[lastLocal - 1];
    const int beg0 = mF.x, len0 = mL.x + mL.y - mF.x;
    const int beg1 = mF.z, len1 = mL.z + mL.w - mF.z;
    for (int i = tid; i < min(len0, CAPI); i += 256) s_idx[0][i] = __ldg(&d_csr[0][beg0 + i]);
    for (int i = tid; i < min(len1, CAPI); i += 256) s_idx[1][i] = __ldg(&d_csr[1][beg1 + i]);
    __syncthreads();

    const bool fastI = (len0 <= CAPI) && (len1 <= CAPI);

    // ---- gather: 2 passes of 4 nodes per warp ----
    if (fastI) {
        #pragma unroll
        for (int pass = 0; pass < 2; pass++)
            gather_pass<true >(warp * 8 + pass * 4 + q, xin, s_meta, beg0, beg1,
                               s_idx, cq, s_x, s_h[0], s_h[1]);
    } else {
        #pragma unroll
        for (int pass = 0; pass < 2; pass++)
            gather_pass<false>(warp * 8 + pass * 4 + q, xin, s_meta, beg0, beg1,
                               s_idx, cq, s_x, s_h[0], s_h[1]);
    }
    __syncthreads();

    // ---- GEMM + epilogue: warps 0..3, warp = m-tile (16 nodes), both dirs ----
    if (warp < 4) {
        const int g  = lane >> 2;
        const int t  = lane & 3;
        const int m0 = warp * 16;

        float acc0[4][4], acc1[4][4];
        #pragma unroll
        for (int nt = 0; nt < 4; nt++)
            #pragma unroll
            for (int i = 0; i < 4; i++) { acc0[nt][i] = 0.f; acc1[nt][i] = 0.f; }

        #pragma unroll
        for (int kt = 0; kt < 32; kt += 16) {
            uint32_t a0 = *(const uint32_t*)&s_h[0][m0 + g    ][kt + t * 2];
            uint32_t a1 = *(const uint32_t*)&s_h[0][m0 + g + 8][kt + t * 2];
            uint32_t a2 = *(const uint32_t*)&s_h[0][m0 + g    ][kt + t * 2 + 8];
            uint32_t a3 = *(const uint32_t*)&s_h[0][m0 + g + 8][kt + t * 2 + 8];
            #pragma unroll
            for (int nt = 0; nt < 4; nt++) {
                uint32_t b0 = *(const uint32_t*)&s_wt[0][nt * 8 + g][kt + t * 2];
                uint32_t b1 = *(const uint32_t*)&s_wt[0][nt * 8 + g][kt + t * 2 + 8];
                mma_16816(acc0[nt], a0, a1, a2, a3, b0, b1);
            }
            a0 = *(const uint32_t*)&s_h[1][m0 + g    ][kt + t * 2];
            a1 = *(const uint32_t*)&s_h[1][m0 + g + 8][kt + t * 2];
            a2 = *(const uint32_t*)&s_h[1][m0 + g    ][kt + t * 2 + 8];
            a3 = *(const uint32_t*)&s_h[1][m0 + g + 8][kt + t * 2 + 8];
            #pragma unroll
            for (int nt = 0; nt < 4; nt++) {
                uint32_t b0 = *(const uint32_t*)&s_wt[1][nt * 8 + g][kt + t * 2];
                uint32_t b1 = *(const uint32_t*)&s_wt[1][nt * 8 + g][kt + t * 2 + 8];
                mma_16816(acc1[nt], a0, a1, a2, a3, b0, b1);
            }
        }

        int node0 = blockBase + m0 + g;
        int node1 = node0 + 8;
        #pragma unroll
        for (int nt = 0; nt < 4; nt++) {
            int col = nt * 8 + t * 2;
            float2 xv0 = __half22float2(*(__half2*)&s_x[m0 + g    ][col]);
            float2 xv1 = __half22float2(*(__half2*)&s_x[m0 + g + 8][col]);
            float o00 = xv0.x + fmaxf(acc0[nt][0], 0.f) + fmaxf(acc1[nt][0], 0.f);
            float o01 = xv0.y + fmaxf(acc0[nt][1], 0.f) + fmaxf(acc1[nt][1], 0.f);
            float o10 = xv1.x + fmaxf(acc0[nt][2], 0.f) + fmaxf(acc1[nt][2], 0.f);
            float o11 = xv1.y + fmaxf(acc0[nt][3], 0.f) + fmaxf(acc1[nt][3], 0.f);
            if (node0 < n)
                *(__half2*)&xout[(size_t)node0 * C + col] = __floats2half2_rn(o00, o01);
            if (node1 < n)
                *(__half2*)&xout[(size_t)node1 * C + col] = __floats2half2_rn(o10, o11);
        }
    }
}

// ---------------- pooling: per-graph sum + count (batch sorted) ----------------
__global__ void k_pool(const int* __restrict__ batch, const __half* __restrict__ x, int n)
{
    int lane = threadIdx.x & 31;
    int warp = threadIdx.x >> 5;
    int base = blockIdx.x * 256 + warp * 32;

    float acc = 0.f;
    int cur = -1, run = 0;
    for (int j = 0; j < 32; j++) {
        int node = base + j;
        if (node >= n) break;
        int b = __ldg(batch + node);
        float v = __half2float(__ldg(x + (size_t)node * C + lane));
        if (b != cur) {
            if (cur >= 0) {
                atomicAdd(&d_gsum[cur * C + lane], acc);
                if (lane == 0) atomicAdd(&d_gcnt[cur], (float)run);
            }
            cur = b; acc = 0.f; run = 0;
        }
        acc += v; run++;
    }
    if (cur >= 0) {
        atomicAdd(&d_gsum[cur * C + lane], acc);
        if (lane == 0) atomicAdd(&d_gcnt[cur], (float)run);
    }
}

// ---------------- MLP head: 8 graphs per block; self-cleans pool buffers -------
#define GPB 8
__global__ void k_mlp(const float* __restrict__ hw, const float* __restrict__ hb,
                      const float* __restrict__ ow, float* __restrict__ out)
{
    __shared__ float gs[GPB][C];
    __shared__ float sout[GPB];
    int tid = threadIdx.x;
    if (tid < GPB * C) {
        int g = tid >> 5, c = tid & 31;
        int gb = blockIdx.x * GPB + g;
        gs[g][c] = d_gsum[gb * C + c] / d_gcnt[gb];
    }
    if (tid < GPB) sout[tid] = 0.f;
    __syncthreads();
    if (tid < GPB * C) {
        int g = tid >> 5, c = tid & 31;
        d_gsum[(blockIdx.x * GPB + g) * C + c] = 0.f;
    }
    if (tid < GPB) d_gcnt[blockIdx.x * GPB + tid] = 0.f;

    float part[GPB];
    #pragma unroll
    for (int g = 0; g < GPB; g++) part[g] = 0.f;

    for (int j = tid; j < HIDDEN; j += 256) {
        float h[GPB];
        float bj = __ldg(hb + j);
        #pragma unroll
        for (int g = 0; g < GPB; g++) h[g] = bj;
        #pragma unroll
        for (int k = 0; k < C; k++) {
            float wkj = __ldg(hw + k * HIDDEN + j);
            #pragma unroll
            for (int g = 0; g < GPB; g++)
                h[g] = fmaf(gs[g][k], wkj, h[g]);
        }
        float oj = __ldg(ow + j);
        #pragma unroll
        for (int g = 0; g < GPB; g++)
            part[g] += fmaxf(h[g], 0.f) * oj;
    }
    #pragma unroll
    for (int g = 0; g < GPB; g++) {
        float v = part[g];
        #pragma unroll
        for (int off = 16; off > 0; off >>= 1)
            v += __shfl_down_sync(0xffffffffu, v, off);
        if ((tid & 31) == 0) atomicAdd(&sout[g], v);
    }
    __syncthreads();
    if (tid < GPB) out[blockIdx.x * GPB + tid] = sout[tid];
}

// ---------------- launch ---------------------------------------------------------
extern "C" void kernel_launch(void* const* d_in, const int* in_sizes, int n_in,
                              void* d_out, int out_size)
{
    const int*   nodes    = (const int*)  d_in[0];
    const int*   sources  = (const int*)  d_in[1];
    const int*   targets  = (const int*)  d_in[2];
    const int*   batch    = (const int*)  d_in[3];
    const float* emb      = (const float*)d_in[4];
    const float* conv_w   = (const float*)d_in[5];
    const float* hidden_w = (const float*)d_in[6];
    const float* hidden_b = (const float*)d_in[7];
    const float* out_w    = (const float*)d_in[8];
    float*       out      = (float*)d_out;

    const int N = in_sizes[0];
    const int E = in_sizes[1];

    // CSR build: hist (+flag reset), single-pass scan, scatter+init
    k_hist        <<<(E + 255) / 256, 256>>>(sources, targets, E);
    k_scan        <<<dim3(NBLK, 2), SCAN_BLK>>>();
    k_scatter_init<<<(N * C + 255) / 256, 256>>>(sources, targets, nodes, emb, E, N);

    // 8 fused layers, ping-pong (even count -> final in buffer 0)
    const int nb = (N + 63) / 64;
    __half* xh = nullptr;
    cudaGetSymbolAddress((void**)&xh, d_xh);
    __half* xa = xh;
    __half* xb = xh + (size_t)N_NODES * C;
    for (int l = 0; l < LAYERS; l++) {
        const float* wl = conv_w + (size_t)l * 2 * C * C;
        if ((l & 1) == 0) k_layer<<<nb, 256>>>(xa, xb, wl, N);
        else              k_layer<<<nb, 256>>>(xb, xa, wl, N);
    }
    k_pool<<<(N + 255) / 256, 256>>>(batch, xa, N);

    k_mlp<<<NGRAPH / GPB, 256>>>(hidden_w, hidden_b, out_w, out);
}